// round 14
// baseline (speedup 1.0000x reference)
#include <cuda_runtime.h>
#include <cuda_fp16.h>
#include <mma.h>
#include <math.h>

using namespace nvcuda;

#define NN   50000
#define EE   500000
#define PP   10000
#define FIN  128
#define HH   256
#define ETOT (EE + NN)

// -------- scratch (static device globals; no allocs allowed) --------
__device__ __half g_f16 [(size_t)NN * FIN];  // feat fp16; later reused as agg2 out
__device__ __half g_aggx[(size_t)NN * FIN];  // layer1 aggregate of x (pre-GEMM)
__device__ __half g_r16 [(size_t)NN * HH];   // relu(aggx@W1+b1) = gemm2 input
__device__ __half g_h2  [(size_t)NN * FIN];  // gemm2 out
__device__ __half g_w1h [FIN * HH];
__device__ __half g_w2h [HH * FIN];
__device__ __align__(16) float g_ws1[FIN];
__device__ __align__(16) float g_wd1[FIN];
__device__ __align__(16) float g_ws2[HH];
__device__ __align__(16) float g_wd2[HH];
__device__ float  g_es1 [NN];
__device__ float  g_ed1 [NN];
__device__ float  g_es2 [NN];
__device__ float  g_ed2 [NN];
__device__ int    g_deg [NN];
__device__ int    g_rowp[NN + 1];
__device__ int    g_curs[NN];
__device__ int    g_csrc[ETOT];

// side stream + fork/join events (created at DSO load)
struct HxSideStream {
    cudaStream_t s1;
    cudaEvent_t  e0, e1, e2, e3;
    HxSideStream() {
        cudaStreamCreateWithFlags(&s1, cudaStreamNonBlocking);
        cudaEventCreateWithFlags(&e0, cudaEventDisableTiming);
        cudaEventCreateWithFlags(&e1, cudaEventDisableTiming);
        cudaEventCreateWithFlags(&e2, cudaEventDisableTiming);
        cudaEventCreateWithFlags(&e3, cudaEventDisableTiming);
    }
};
static HxSideStream hx;

// ---------------------------------------------------------------
// prep (80 blocks): W->fp16 (0..31), ws1/wd1 (32..47), ws2/wd2 (48..79)
// ---------------------------------------------------------------
__global__ __launch_bounds__(256) void k_prep(
    const float* __restrict__ W1, const float* __restrict__ W2,
    const float* __restrict__ as1, const float* __restrict__ ad1,
    const float* __restrict__ as2, const float* __restrict__ ad2,
    __half* __restrict__ w1h, __half* __restrict__ w2h,
    float* __restrict__ ws1, float* __restrict__ wd1,
    float* __restrict__ ws2, float* __restrict__ wd2)
{
    const int gid  = blockIdx.x;
    const int tid  = threadIdx.x;
    const int wid  = tid >> 5;
    const int lane = tid & 31;

    if (gid < 16) {
        int i = gid * 2048 + tid;
        #pragma unroll
        for (int t = 0; t < 8; t++, i += 256) w1h[i] = __float2half(W1[i]);
    } else if (gid < 32) {
        int i = (gid - 16) * 2048 + tid;
        #pragma unroll
        for (int t = 0; t < 8; t++, i += 256) w2h[i] = __float2half(W2[i]);
    } else if (gid < 48) {
        int r = (gid - 32) * 8 + wid;     // 0..127
        const float* row = W1 + (size_t)r * HH;
        float s = 0.f, d = 0.f;
        for (int o = lane; o < HH; o += 32) {
            float w = row[o];
            s += w * as1[o];
            d += w * ad1[o];
        }
        #pragma unroll
        for (int o = 16; o; o >>= 1) {
            s += __shfl_xor_sync(0xffffffffu, s, o);
            d += __shfl_xor_sync(0xffffffffu, d, o);
        }
        if (lane == 0) { ws1[r] = s; wd1[r] = d; }
    } else {
        int r = (gid - 48) * 8 + wid;     // 0..255
        const float* row = W2 + (size_t)r * FIN;
        float s = 0.f, d = 0.f;
        for (int o = lane; o < FIN; o += 32) {
            float w = row[o];
            s += w * as2[o];
            d += w * ad2[o];
        }
        #pragma unroll
        for (int o = 16; o; o >>= 1) {
            s += __shfl_xor_sync(0xffffffffu, s, o);
            d += __shfl_xor_sync(0xffffffffu, d, o);
        }
        if (lane == 0) { ws2[r] = s; wd2[r] = d; }
    }
}

// ---------------------------------------------------------------
// fused: features fp32 -> fp16 + esed1 dots (warp per node)
// ---------------------------------------------------------------
__global__ __launch_bounds__(256) void k_feat_esed(
    const float* __restrict__ x, __half* __restrict__ f16,
    const float* __restrict__ ws, const float* __restrict__ wd,
    float* __restrict__ es, float* __restrict__ ed)
{
    int w    = (blockIdx.x * blockDim.x + threadIdx.x) >> 5;
    int lane = threadIdx.x & 31;
    if (w >= NN) return;
    float4 v = *reinterpret_cast<const float4*>(x + (size_t)w * FIN + lane * 4);
    float4 a = *reinterpret_cast<const float4*>(ws + lane * 4);
    float4 b = *reinterpret_cast<const float4*>(wd + lane * 4);
    float s = v.x * a.x + v.y * a.y + v.z * a.z + v.w * a.w;
    float d = v.x * b.x + v.y * b.y + v.z * b.z + v.w * b.w;
    __half2 h0 = __floats2half2_rn(v.x, v.y);
    __half2 h1 = __floats2half2_rn(v.z, v.w);
    uint2 out;
    out.x = *(unsigned*)&h0; out.y = *(unsigned*)&h1;
    *reinterpret_cast<uint2*>(f16 + (size_t)w * FIN + lane * 4) = out;
    #pragma unroll
    for (int o = 16; o; o >>= 1) {
        s += __shfl_xor_sync(0xffffffffu, s, o);
        d += __shfl_xor_sync(0xffffffffu, d, o);
    }
    if (lane == 0) { es[w] = s; ed[w] = d; }
}

// ---------------------------------------------------------------
// esed on fp16 rows (warp per node): es=row.ws, ed=row.wd
// ---------------------------------------------------------------
__global__ __launch_bounds__(256) void k_esed_h(
    const __half2* __restrict__ h, const float2* __restrict__ ws2,
    const float2* __restrict__ wd2, float* __restrict__ es,
    float* __restrict__ ed, int dim2)
{
    int w    = (blockIdx.x * blockDim.x + threadIdx.x) >> 5;
    int lane = threadIdx.x & 31;
    if (w >= NN) return;
    const __half2* row = h + (size_t)w * dim2;
    float s = 0.f, d = 0.f;
    for (int j = lane; j < dim2; j += 32) {
        float2 v = __half22float2(row[j]);
        float2 a = ws2[j], b = wd2[j];
        s += v.x * a.x + v.y * a.y;
        d += v.x * b.x + v.y * b.y;
    }
    #pragma unroll
    for (int o = 16; o; o >>= 1) {
        s += __shfl_xor_sync(0xffffffffu, s, o);
        d += __shfl_xor_sync(0xffffffffu, d, o);
    }
    if (lane == 0) { es[w] = s; ed[w] = d; }
}

// ---------------------------------------------------------------
// FP16 GEMM, cp.async.ca double-buffered; 2 blocks/SM.
// EPI: fused bias + relu in epilogue.
// ---------------------------------------------------------------
__device__ __forceinline__ void cp16(void* smem, const void* gmem, int srcBytes)
{
    unsigned saddr = (unsigned)__cvta_generic_to_shared(smem);
    asm volatile("cp.async.ca.shared.global [%0], [%1], 16, %2;\n"
                 :: "r"(saddr), "l"(gmem), "r"(srcBytes));
}

#define LDA 40
#define LDB 136
#define ASZ (128 * LDA)
#define BSZ (32 * LDB)

template<int KDIM, int MDIM, bool EPI>
__global__ __launch_bounds__(256, 2) void k_gemm16(
    const __half* __restrict__ A, const __half* __restrict__ B,
    __half* __restrict__ C, const float* __restrict__ bias, int n)
{
    constexpr int NT = KDIM / 32;
    __shared__ __align__(16) unsigned char sm[2 * (ASZ + BSZ) * 2];
    __half* As[2] = {(__half*)sm, (__half*)(sm + 2 * ASZ)};
    __half* Bs[2] = {(__half*)(sm + 4 * ASZ), (__half*)(sm + 4 * ASZ + 2 * BSZ)};
    float*  Cs    = (float*)sm;

    const int tid  = threadIdx.x;
    const int wid  = tid >> 5;
    const int wr   = wid >> 1;
    const int wc   = wid & 1;
    const int rowBase = blockIdx.y * 128;
    const int colBase = blockIdx.x * 128;

    wmma::fragment<wmma::accumulator, 16, 16, 16, float> acc[2][4];
    #pragma unroll
    for (int i = 0; i < 2; i++)
        #pragma unroll
        for (int j = 0; j < 4; j++)
            wmma::fill_fragment(acc[i][j], 0.f);

    auto loadStage = [&](int s, int k0) {
        #pragma unroll
        for (int t = 0; t < 2; t++) {
            int c  = tid + t * 256;
            int r  = c >> 2, c4 = c & 3;
            int gr = rowBase + r;
            int ok = (gr < n) ? 16 : 0;
            if (gr >= n) gr = n - 1;
            cp16(As[s] + r * LDA + c4 * 8,
                 A + (size_t)gr * KDIM + k0 + c4 * 8, ok);
        }
        #pragma unroll
        for (int t = 0; t < 2; t++) {
            int c = tid + t * 256;
            int r = c >> 4, c8 = c & 15;
            cp16(Bs[s] + r * LDB + c8 * 8,
                 B + (size_t)(k0 + r) * MDIM + colBase + c8 * 8, 16);
        }
        asm volatile("cp.async.commit_group;\n");
    };

    loadStage(0, 0);
    #pragma unroll
    for (int kt = 0; kt < NT; kt++) {
        if (kt + 1 < NT) {
            loadStage((kt + 1) & 1, (kt + 1) * 32);
            asm volatile("cp.async.wait_group 1;\n");
        } else {
            asm volatile("cp.async.wait_group 0;\n");
        }
        __syncthreads();
        const __half* ab = As[kt & 1];
        const __half* bb = Bs[kt & 1];
        #pragma unroll
        for (int kk = 0; kk < 32; kk += 16) {
            wmma::fragment<wmma::matrix_a, 16, 16, 16, __half, wmma::row_major> af[2];
            wmma::fragment<wmma::matrix_b, 16, 16, 16, __half, wmma::row_major> bf[4];
            #pragma unroll
            for (int i = 0; i < 2; i++)
                wmma::load_matrix_sync(af[i], ab + (wr * 32 + i * 16) * LDA + kk, LDA);
            #pragma unroll
            for (int j = 0; j < 4; j++)
                wmma::load_matrix_sync(bf[j], bb + kk * LDB + wc * 64 + j * 16, LDB);
            #pragma unroll
            for (int i = 0; i < 2; i++)
                #pragma unroll
                for (int j = 0; j < 4; j++)
                    wmma::mma_sync(acc[i][j], af[i], bf[j], acc[i][j]);
        }
        __syncthreads();
    }

    #pragma unroll
    for (int ph = 0; ph < 2; ph++) {
        if (wc == ph) {
            #pragma unroll
            for (int i = 0; i < 2; i++)
                #pragma unroll
                for (int j = 0; j < 4; j++)
                    wmma::store_matrix_sync(Cs + (wr * 32 + i * 16) * 64 + j * 16,
                                            acc[i][j], 64, wmma::mem_row_major);
        }
        __syncthreads();
        #pragma unroll
        for (int c = tid; c < 128 * 8; c += 256) {
            int r  = c >> 3, c8 = c & 7;
            int gr = rowBase + r;
            if (gr < n) {
                const float4* p = (const float4*)(Cs + r * 64 + c8 * 8);
                float4 u0 = p[0], u1 = p[1];
                if (EPI) {
                    const float* bp = bias + colBase + ph * 64 + c8 * 8;
                    float4 b0 = *reinterpret_cast<const float4*>(bp);
                    float4 b1v = *reinterpret_cast<const float4*>(bp + 4);
                    u0.x = fmaxf(u0.x + b0.x, 0.f);  u0.y = fmaxf(u0.y + b0.y, 0.f);
                    u0.z = fmaxf(u0.z + b0.z, 0.f);  u0.w = fmaxf(u0.w + b0.w, 0.f);
                    u1.x = fmaxf(u1.x + b1v.x, 0.f); u1.y = fmaxf(u1.y + b1v.y, 0.f);
                    u1.z = fmaxf(u1.z + b1v.z, 0.f); u1.w = fmaxf(u1.w + b1v.w, 0.f);
                }
                __half2 h0 = __floats2half2_rn(u0.x, u0.y);
                __half2 h1 = __floats2half2_rn(u0.z, u0.w);
                __half2 h2 = __floats2half2_rn(u1.x, u1.y);
                __half2 h3 = __floats2half2_rn(u1.z, u1.w);
                uint4 out;
                out.x = *(unsigned*)&h0; out.y = *(unsigned*)&h1;
                out.z = *(unsigned*)&h2; out.w = *(unsigned*)&h3;
                *(uint4*)(C + (size_t)gr * MDIM + colBase + ph * 64 + c8 * 8) = out;
            }
        }
        __syncthreads();
    }
}

// ---------------------------------------------------------------
// CSR build (side stream; R12 exact)
// ---------------------------------------------------------------
__device__ __forceinline__ int edge_src(const int* ei, int e) { return (e < EE) ? ei[e]      : e - EE; }
__device__ __forceinline__ int edge_dst(const int* ei, int e) { return (e < EE) ? ei[EE + e] : e - EE; }

__global__ void k_zero(int* __restrict__ deg)
{
    int i = blockIdx.x * blockDim.x + threadIdx.x;
    if (i < NN) deg[i] = 0;
}

__global__ __launch_bounds__(256) void k_hist(const int* __restrict__ ei, int* __restrict__ deg)
{
    int e = blockIdx.x * blockDim.x + threadIdx.x;
    if (e < ETOT) atomicAdd(&deg[edge_dst(ei, e)], 1);
}

#define SCAN_T 1024
__global__ __launch_bounds__(SCAN_T) void k_scan_fused(
    const int* __restrict__ deg, int* __restrict__ rowp, int* __restrict__ curs)
{
    __shared__ int sd[SCAN_T];
    const int tid   = threadIdx.x;
    const int chunk = (NN + SCAN_T - 1) / SCAN_T;
    const int base  = tid * chunk;
    int sum = 0;
    for (int j = 0; j < chunk; j++) {
        int i = base + j;
        if (i < NN) sum += deg[i];
    }
    sd[tid] = sum;
    __syncthreads();
    for (int off = 1; off < SCAN_T; off <<= 1) {
        int t = (tid >= off) ? sd[tid - off] : 0;
        __syncthreads();
        sd[tid] += t;
        __syncthreads();
    }
    int run = sd[tid] - sum;
    for (int j = 0; j < chunk; j++) {
        int i = base + j;
        if (i < NN) {
            rowp[i] = run;
            curs[i] = run;
            run += deg[i];
        }
    }
    if (tid == 0) rowp[NN] = ETOT;
}

__global__ __launch_bounds__(256) void k_scatter(const int* __restrict__ ei,
    int* __restrict__ curs, int* __restrict__ csrc)
{
    int e = blockIdx.x * blockDim.x + threadIdx.x;
    if (e >= ETOT) return;
    int d = edge_dst(ei, e);
    int pos = atomicAdd(&curs[d], 1);
    csrc[pos] = edge_src(ei, e);
}

// ---------------------------------------------------------------
// fused GAT softmax + aggregate (warp per dst, CSR; DIM=128, exp inline,
// R12-proven 2x unroll). Optional bias; fp16 output.
// ---------------------------------------------------------------
template<bool BIAS>
__global__ __launch_bounds__(256) void k_gat_agg(
    const __half* __restrict__ h16, const float* __restrict__ es,
    const float* __restrict__ ed, const int* __restrict__ rowp,
    const int* __restrict__ csrc, const float* __restrict__ bias,
    __half* __restrict__ outH)
{
    int w    = (blockIdx.x * blockDim.x + threadIdx.x) >> 5;
    int lane = threadIdx.x & 31;
    if (w >= NN) return;

    int start = rowp[w];
    int end   = rowp[w + 1];
    float edv = ed[w];

    float den = 0.f;
    for (int base = start; base < end; base += 32) {
        int e = base + lane;
        float p = 0.f;
        if (e < end) {
            float x = es[csrc[e]] + edv;
            x = (x >= 0.f) ? x : 0.2f * x;
            p = __expf(x);
        }
        den += p;
    }
    #pragma unroll
    for (int o = 16; o; o >>= 1) den += __shfl_xor_sync(0xffffffffu, den, o);
    float inv = 1.f / den;

    float acc[4] = {};
    for (int base = start; base < end; base += 32) {
        int e = base + lane;
        int sl = 0;
        float p = 0.f;
        if (e < end) {
            sl = csrc[e];
            float x = es[sl] + edv;
            x = (x >= 0.f) ? x : 0.2f * x;
            p = __expf(x);
        }
        int cnt = min(32, end - base);
        int j = 0;
        for (; j + 2 <= cnt; j += 2) {
            int   s0 = __shfl_sync(0xffffffffu, sl, j);
            float a0 = __shfl_sync(0xffffffffu, p,  j) * inv;
            int   s1 = __shfl_sync(0xffffffffu, sl, j + 1);
            float a1 = __shfl_sync(0xffffffffu, p,  j + 1) * inv;
            uint2 r0 = *reinterpret_cast<const uint2*>(h16 + (size_t)s0 * FIN + lane * 4);
            uint2 r1 = *reinterpret_cast<const uint2*>(h16 + (size_t)s1 * FIN + lane * 4);
            const __half2* q0 = reinterpret_cast<const __half2*>(&r0);
            const __half2* q1 = reinterpret_cast<const __half2*>(&r1);
            #pragma unroll
            for (int t = 0; t < 2; t++) {
                float2 f0 = __half22float2(q0[t]);
                float2 f1 = __half22float2(q1[t]);
                acc[t * 2 + 0] += a0 * f0.x + a1 * f1.x;
                acc[t * 2 + 1] += a0 * f0.y + a1 * f1.y;
            }
        }
        for (; j < cnt; j++) {
            int   s0 = __shfl_sync(0xffffffffu, sl, j);
            float a0 = __shfl_sync(0xffffffffu, p,  j) * inv;
            uint2 r0 = *reinterpret_cast<const uint2*>(h16 + (size_t)s0 * FIN + lane * 4);
            const __half2* q0 = reinterpret_cast<const __half2*>(&r0);
            #pragma unroll
            for (int t = 0; t < 2; t++) {
                float2 f0 = __half22float2(q0[t]);
                acc[t * 2 + 0] += a0 * f0.x;
                acc[t * 2 + 1] += a0 * f0.y;
            }
        }
    }

    float v[4] = {acc[0], acc[1], acc[2], acc[3]};
    if (BIAS) {
        float4 b = *reinterpret_cast<const float4*>(bias + lane * 4);
        v[0] += b.x; v[1] += b.y; v[2] += b.z; v[3] += b.w;
    }
    __half2 hh[2];
    hh[0] = __floats2half2_rn(v[0], v[1]);
    hh[1] = __floats2half2_rn(v[2], v[3]);
    *reinterpret_cast<uint2*>(outH + (size_t)w * FIN + lane * 4) =
        *reinterpret_cast<uint2*>(hh);
}

// ---------------------------------------------------------------
// link predictor (warp/pair, fp16 h)
// ---------------------------------------------------------------
__global__ __launch_bounds__(256) void k_link_pred(
    const __half* __restrict__ h, const int* __restrict__ mask,
    const float* __restrict__ Wl, const float* __restrict__ bl,
    float* __restrict__ out)
{
    int warp = (blockIdx.x * blockDim.x + threadIdx.x) >> 5;
    int lane = threadIdx.x & 31;
    if (warp >= PP) return;
    int m0 = mask[warp * 2 + 0];
    int m1 = mask[warp * 2 + 1];
    uint2 r0 = *reinterpret_cast<const uint2*>(h + (size_t)m0 * FIN + lane * 4);
    uint2 r1 = *reinterpret_cast<const uint2*>(h + (size_t)m1 * FIN + lane * 4);
    float4 w0 = *reinterpret_cast<const float4*>(Wl + lane * 4);
    float4 w1 = *reinterpret_cast<const float4*>(Wl + FIN + lane * 4);
    const __half2* q0 = reinterpret_cast<const __half2*>(&r0);
    const __half2* q1 = reinterpret_cast<const __half2*>(&r1);
    float2 a0 = __half22float2(q0[0]), a1 = __half22float2(q0[1]);
    float2 b0 = __half22float2(q1[0]), b1 = __half22float2(q1[1]);
    float acc = a0.x * w0.x + a0.y * w0.y + a1.x * w0.z + a1.y * w0.w
              + b0.x * w1.x + b0.y * w1.y + b1.x * w1.z + b1.y * w1.w;
    #pragma unroll
    for (int o = 16; o; o >>= 1) acc += __shfl_xor_sync(0xffffffffu, acc, o);
    if (lane == 0) out[warp] = 1.f / (1.f + __expf(-(acc + bl[0])));
}

// ---------------------------------------------------------------
extern "C" void kernel_launch(void* const* d_in, const int* in_sizes, int n_in,
                              void* d_out, int out_size)
{
    const float* features = (const float*)d_in[0];
    const int*   ei       = (const int*)  d_in[1];
    const int*   mask     = (const int*)  d_in[2];
    const float* W1       = (const float*)d_in[3];
    const float* a_src1   = (const float*)d_in[4];
    const float* a_dst1   = (const float*)d_in[5];
    const float* b1       = (const float*)d_in[6];
    const float* W2       = (const float*)d_in[7];
    const float* a_src2   = (const float*)d_in[8];
    const float* a_dst2   = (const float*)d_in[9];
    const float* b2       = (const float*)d_in[10];
    const float* Wl       = (const float*)d_in[11];
    const float* bl       = (const float*)d_in[12];
    float* out = (float*)d_out;

    __half *f16, *aggx, *r16, *h2, *w1h, *w2h;
    float  *ws1, *wd1, *ws2, *wd2, *es1, *ed1, *es2, *ed2;
    int *deg, *rowp, *curs, *csrc;
    cudaGetSymbolAddress((void**)&f16,  g_f16);
    cudaGetSymbolAddress((void**)&aggx, g_aggx);
    cudaGetSymbolAddress((void**)&r16,  g_r16);
    cudaGetSymbolAddress((void**)&h2,   g_h2);
    cudaGetSymbolAddress((void**)&w1h,  g_w1h);
    cudaGetSymbolAddress((void**)&w2h,  g_w2h);
    cudaGetSymbolAddress((void**)&ws1,  g_ws1);
    cudaGetSymbolAddress((void**)&wd1,  g_wd1);
    cudaGetSymbolAddress((void**)&ws2,  g_ws2);
    cudaGetSymbolAddress((void**)&wd2,  g_wd2);
    cudaGetSymbolAddress((void**)&es1,  g_es1);
    cudaGetSymbolAddress((void**)&ed1,  g_ed1);
    cudaGetSymbolAddress((void**)&es2,  g_es2);
    cudaGetSymbolAddress((void**)&ed2,  g_ed2);
    cudaGetSymbolAddress((void**)&deg,  g_deg);
    cudaGetSymbolAddress((void**)&rowp, g_rowp);
    cudaGetSymbolAddress((void**)&curs, g_curs);
    cudaGetSymbolAddress((void**)&csrc, g_csrc);

    const int edgeBlocks     = (ETOT + 255) / 256;
    const int nodeWarpBlocks = (NN * 32 + 255) / 256;

    // fork: CSR chain on side stream (depends only on ei)
    cudaEventRecord(hx.e0, 0);
    cudaStreamWaitEvent(hx.s1, hx.e0, 0);

    // main: (1) prep  (2) feat+esed1
    k_prep<<<80, 256>>>(W1, W2, a_src1, a_dst1, a_src2, a_dst2,
                        w1h, w2h, ws1, wd1, ws2, wd2);
    k_feat_esed<<<nodeWarpBlocks, 256>>>(features, f16, ws1, wd1, es1, ed1);
    // side: CSR
    k_zero      <<<(NN + 255) / 256, 256, 0, hx.s1>>>(deg);
    k_hist      <<<edgeBlocks, 256, 0, hx.s1>>>(ei, deg);
    k_scan_fused<<<1, SCAN_T, 0, hx.s1>>>(deg, rowp, curs);
    k_scatter   <<<edgeBlocks, 256, 0, hx.s1>>>(ei, curs, csrc);
    cudaEventRecord(hx.e1, hx.s1);

    // join: aggregate layer1 on x (128-dim gathers, pre-GEMM)
    cudaStreamWaitEvent(0, hx.e1, 0);
    k_gat_agg<false><<<nodeWarpBlocks, 256>>>(f16, es1, ed1, rowp, csrc, nullptr, aggx);

    // gemm1: r16 = relu(aggx@W1 + b1)
    {
        dim3 g(HH / 128, (NN + 127) / 128);
        k_gemm16<FIN, HH, true><<<g, 256>>>(aggx, w1h, r16, b1, NN);
    }
    cudaEventRecord(hx.e2, 0);

    // side: esed2 on r16 (concurrent with gemm2; both read-only on r16)
    cudaStreamWaitEvent(hx.s1, hx.e2, 0);
    k_esed_h<<<nodeWarpBlocks, 256, 0, hx.s1>>>((const __half2*)r16,
        (const float2*)ws2, (const float2*)wd2, es2, ed2, HH / 2);
    cudaEventRecord(hx.e3, hx.s1);

    // main: gemm2: h2 = r16@W2 (no epilogue; bias b2 in agg2)
    {
        dim3 g(FIN / 128, (NN + 127) / 128);
        k_gemm16<HH, FIN, false><<<g, 256>>>(r16, w2h, h2, nullptr, NN);
    }

    // join esed2; aggregate layer2 on h2 (128-dim), bias b2, out -> f16 buf
    cudaStreamWaitEvent(0, hx.e3, 0);
    k_gat_agg<true><<<nodeWarpBlocks, 256>>>(h2, es2, ed2, rowp, csrc, b2, f16);

    // link predictor
    k_link_pred<<<(PP * 32 + 255) / 256, 256>>>(f16, mask, Wl, bl, out);
}

// round 15
// speedup vs baseline: 1.1034x; 1.1034x over previous
#include <cuda_runtime.h>
#include <cuda_fp16.h>
#include <mma.h>
#include <math.h>

using namespace nvcuda;

#define NN   50000
#define EE   500000
#define PP   10000
#define FIN  128
#define HH   256
#define ETOT (EE + NN)

// -------- scratch (static device globals; no allocs allowed) --------
__device__ __half g_f16 [(size_t)NN * FIN];  // feat fp16; later reused as agg2 out
__device__ __half g_h1  [(size_t)NN * HH];
__device__ __half g_r16 [(size_t)NN * HH];
__device__ __half g_h2  [(size_t)NN * FIN];
__device__ __half g_w1h [FIN * HH];
__device__ __half g_w2h [HH * FIN];
__device__ __align__(16) float g_ws1[FIN];
__device__ __align__(16) float g_wd1[FIN];
__device__ __align__(16) float g_ws2[HH];
__device__ __align__(16) float g_wd2[HH];
__device__ float  g_es1 [NN];
__device__ float  g_ed1 [NN];
__device__ float  g_es2 [NN];
__device__ float  g_ed2 [NN];
__device__ int    g_deg [NN];
__device__ int    g_rowp[NN + 1];
__device__ int    g_curs[NN];
__device__ int    g_csrc[ETOT];

// side stream + fork/join events (created at DSO load)
struct HxSideStream {
    cudaStream_t s1;
    cudaEvent_t  e0, e1;
    HxSideStream() {
        cudaStreamCreateWithFlags(&s1, cudaStreamNonBlocking);
        cudaEventCreateWithFlags(&e0, cudaEventDisableTiming);
        cudaEventCreateWithFlags(&e1, cudaEventDisableTiming);
    }
};
static HxSideStream hx;

// ---------------------------------------------------------------
// prep (80 blocks): W->fp16 (0..31), ws1/wd1 (32..47), ws2/wd2 (48..79)
// ---------------------------------------------------------------
__global__ __launch_bounds__(256) void k_prep(
    const float* __restrict__ W1, const float* __restrict__ W2,
    const float* __restrict__ as1, const float* __restrict__ ad1,
    const float* __restrict__ as2, const float* __restrict__ ad2,
    __half* __restrict__ w1h, __half* __restrict__ w2h,
    float* __restrict__ ws1, float* __restrict__ wd1,
    float* __restrict__ ws2, float* __restrict__ wd2)
{
    const int gid  = blockIdx.x;
    const int tid  = threadIdx.x;
    const int wid  = tid >> 5;
    const int lane = tid & 31;

    if (gid < 16) {
        int i = gid * 2048 + tid;
        #pragma unroll
        for (int t = 0; t < 8; t++, i += 256) w1h[i] = __float2half(W1[i]);
    } else if (gid < 32) {
        int i = (gid - 16) * 2048 + tid;
        #pragma unroll
        for (int t = 0; t < 8; t++, i += 256) w2h[i] = __float2half(W2[i]);
    } else if (gid < 48) {
        int r = (gid - 32) * 8 + wid;     // 0..127
        const float* row = W1 + (size_t)r * HH;
        float s = 0.f, d = 0.f;
        for (int o = lane; o < HH; o += 32) {
            float w = row[o];
            s += w * as1[o];
            d += w * ad1[o];
        }
        #pragma unroll
        for (int o = 16; o; o >>= 1) {
            s += __shfl_xor_sync(0xffffffffu, s, o);
            d += __shfl_xor_sync(0xffffffffu, d, o);
        }
        if (lane == 0) { ws1[r] = s; wd1[r] = d; }
    } else {
        int r = (gid - 48) * 8 + wid;     // 0..255
        const float* row = W2 + (size_t)r * FIN;
        float s = 0.f, d = 0.f;
        for (int o = lane; o < FIN; o += 32) {
            float w = row[o];
            s += w * as2[o];
            d += w * ad2[o];
        }
        #pragma unroll
        for (int o = 16; o; o >>= 1) {
            s += __shfl_xor_sync(0xffffffffu, s, o);
            d += __shfl_xor_sync(0xffffffffu, d, o);
        }
        if (lane == 0) { ws2[r] = s; wd2[r] = d; }
    }
}

// ---------------------------------------------------------------
// fused: features fp32 -> fp16 + esed1 dots (warp per node)
// ---------------------------------------------------------------
__global__ __launch_bounds__(256) void k_feat_esed(
    const float* __restrict__ x, __half* __restrict__ f16,
    const float* __restrict__ ws, const float* __restrict__ wd,
    float* __restrict__ es, float* __restrict__ ed)
{
    int w    = (blockIdx.x * blockDim.x + threadIdx.x) >> 5;
    int lane = threadIdx.x & 31;
    if (w >= NN) return;
    float4 v = *reinterpret_cast<const float4*>(x + (size_t)w * FIN + lane * 4);
    float4 a = *reinterpret_cast<const float4*>(ws + lane * 4);
    float4 b = *reinterpret_cast<const float4*>(wd + lane * 4);
    float s = v.x * a.x + v.y * a.y + v.z * a.z + v.w * a.w;
    float d = v.x * b.x + v.y * b.y + v.z * b.z + v.w * b.w;
    __half2 h0 = __floats2half2_rn(v.x, v.y);
    __half2 h1 = __floats2half2_rn(v.z, v.w);
    uint2 out;
    out.x = *(unsigned*)&h0; out.y = *(unsigned*)&h1;
    *reinterpret_cast<uint2*>(f16 + (size_t)w * FIN + lane * 4) = out;
    #pragma unroll
    for (int o = 16; o; o >>= 1) {
        s += __shfl_xor_sync(0xffffffffu, s, o);
        d += __shfl_xor_sync(0xffffffffu, d, o);
    }
    if (lane == 0) { es[w] = s; ed[w] = d; }
}

// ---------------------------------------------------------------
// FP16 GEMM, cp.async.ca double-buffered; 2 blocks/SM (R9-measured)
// ---------------------------------------------------------------
__device__ __forceinline__ void cp16(void* smem, const void* gmem, int srcBytes)
{
    unsigned saddr = (unsigned)__cvta_generic_to_shared(smem);
    asm volatile("cp.async.ca.shared.global [%0], [%1], 16, %2;\n"
                 :: "r"(saddr), "l"(gmem), "r"(srcBytes));
}

#define LDA 40
#define LDB 136
#define ASZ (128 * LDA)
#define BSZ (32 * LDB)

template<int KDIM, int MDIM>
__global__ __launch_bounds__(256, 2) void k_gemm16(
    const __half* __restrict__ A, const __half* __restrict__ B,
    __half* __restrict__ C, int n)
{
    constexpr int NT = KDIM / 32;
    __shared__ __align__(16) unsigned char sm[2 * (ASZ + BSZ) * 2];
    __half* As[2] = {(__half*)sm, (__half*)(sm + 2 * ASZ)};
    __half* Bs[2] = {(__half*)(sm + 4 * ASZ), (__half*)(sm + 4 * ASZ + 2 * BSZ)};
    float*  Cs    = (float*)sm;

    const int tid  = threadIdx.x;
    const int wid  = tid >> 5;
    const int wr   = wid >> 1;
    const int wc   = wid & 1;
    const int rowBase = blockIdx.y * 128;
    const int colBase = blockIdx.x * 128;

    wmma::fragment<wmma::accumulator, 16, 16, 16, float> acc[2][4];
    #pragma unroll
    for (int i = 0; i < 2; i++)
        #pragma unroll
        for (int j = 0; j < 4; j++)
            wmma::fill_fragment(acc[i][j], 0.f);

    auto loadStage = [&](int s, int k0) {
        #pragma unroll
        for (int t = 0; t < 2; t++) {
            int c  = tid + t * 256;
            int r  = c >> 2, c4 = c & 3;
            int gr = rowBase + r;
            int ok = (gr < n) ? 16 : 0;
            if (gr >= n) gr = n - 1;
            cp16(As[s] + r * LDA + c4 * 8,
                 A + (size_t)gr * KDIM + k0 + c4 * 8, ok);
        }
        #pragma unroll
        for (int t = 0; t < 2; t++) {
            int c = tid + t * 256;
            int r = c >> 4, c8 = c & 15;
            cp16(Bs[s] + r * LDB + c8 * 8,
                 B + (size_t)(k0 + r) * MDIM + colBase + c8 * 8, 16);
        }
        asm volatile("cp.async.commit_group;\n");
    };

    loadStage(0, 0);
    #pragma unroll
    for (int kt = 0; kt < NT; kt++) {
        if (kt + 1 < NT) {
            loadStage((kt + 1) & 1, (kt + 1) * 32);
            asm volatile("cp.async.wait_group 1;\n");
        } else {
            asm volatile("cp.async.wait_group 0;\n");
        }
        __syncthreads();
        const __half* ab = As[kt & 1];
        const __half* bb = Bs[kt & 1];
        #pragma unroll
        for (int kk = 0; kk < 32; kk += 16) {
            wmma::fragment<wmma::matrix_a, 16, 16, 16, __half, wmma::row_major> af[2];
            wmma::fragment<wmma::matrix_b, 16, 16, 16, __half, wmma::row_major> bf[4];
            #pragma unroll
            for (int i = 0; i < 2; i++)
                wmma::load_matrix_sync(af[i], ab + (wr * 32 + i * 16) * LDA + kk, LDA);
            #pragma unroll
            for (int j = 0; j < 4; j++)
                wmma::load_matrix_sync(bf[j], bb + kk * LDB + wc * 64 + j * 16, LDB);
            #pragma unroll
            for (int i = 0; i < 2; i++)
                #pragma unroll
                for (int j = 0; j < 4; j++)
                    wmma::mma_sync(acc[i][j], af[i], bf[j], acc[i][j]);
        }
        __syncthreads();
    }

    #pragma unroll
    for (int ph = 0; ph < 2; ph++) {
        if (wc == ph) {
            #pragma unroll
            for (int i = 0; i < 2; i++)
                #pragma unroll
                for (int j = 0; j < 4; j++)
                    wmma::store_matrix_sync(Cs + (wr * 32 + i * 16) * 64 + j * 16,
                                            acc[i][j], 64, wmma::mem_row_major);
        }
        __syncthreads();
        #pragma unroll
        for (int c = tid; c < 128 * 8; c += 256) {
            int r  = c >> 3, c8 = c & 7;
            int gr = rowBase + r;
            if (gr < n) {
                const float4* p = (const float4*)(Cs + r * 64 + c8 * 8);
                float4 u0 = p[0], u1 = p[1];
                __half2 h0 = __floats2half2_rn(u0.x, u0.y);
                __half2 h1 = __floats2half2_rn(u0.z, u0.w);
                __half2 h2 = __floats2half2_rn(u1.x, u1.y);
                __half2 h3 = __floats2half2_rn(u1.z, u1.w);
                uint4 out;
                out.x = *(unsigned*)&h0; out.y = *(unsigned*)&h1;
                out.z = *(unsigned*)&h2; out.w = *(unsigned*)&h3;
                *(uint4*)(C + (size_t)gr * MDIM + colBase + ph * 64 + c8 * 8) = out;
            }
        }
        __syncthreads();
    }
}

// ---------------------------------------------------------------
// CSR build (side stream)
// ---------------------------------------------------------------
__device__ __forceinline__ int edge_src(const int* ei, int e) { return (e < EE) ? ei[e]      : e - EE; }
__device__ __forceinline__ int edge_dst(const int* ei, int e) { return (e < EE) ? ei[EE + e] : e - EE; }

__global__ void k_zero(int* __restrict__ deg)
{
    int i = blockIdx.x * blockDim.x + threadIdx.x;
    if (i < NN) deg[i] = 0;
}

__global__ __launch_bounds__(256) void k_hist(const int* __restrict__ ei, int* __restrict__ deg)
{
    int e = blockIdx.x * blockDim.x + threadIdx.x;
    if (e < ETOT) atomicAdd(&deg[edge_dst(ei, e)], 1);
}

#define SCAN_T 1024
__global__ __launch_bounds__(SCAN_T) void k_scan_fused(
    const int* __restrict__ deg, int* __restrict__ rowp, int* __restrict__ curs)
{
    __shared__ int sd[SCAN_T];
    const int tid   = threadIdx.x;
    const int chunk = (NN + SCAN_T - 1) / SCAN_T;
    const int base  = tid * chunk;
    int sum = 0;
    for (int j = 0; j < chunk; j++) {
        int i = base + j;
        if (i < NN) sum += deg[i];
    }
    sd[tid] = sum;
    __syncthreads();
    for (int off = 1; off < SCAN_T; off <<= 1) {
        int t = (tid >= off) ? sd[tid - off] : 0;
        __syncthreads();
        sd[tid] += t;
        __syncthreads();
    }
    int run = sd[tid] - sum;
    for (int j = 0; j < chunk; j++) {
        int i = base + j;
        if (i < NN) {
            rowp[i] = run;
            curs[i] = run;
            run += deg[i];
        }
    }
    if (tid == 0) rowp[NN] = ETOT;
}

__global__ __launch_bounds__(256) void k_scatter(const int* __restrict__ ei,
    int* __restrict__ curs, int* __restrict__ csrc)
{
    int e = blockIdx.x * blockDim.x + threadIdx.x;
    if (e >= ETOT) return;
    int d = edge_dst(ei, e);
    int pos = atomicAdd(&curs[d], 1);
    csrc[pos] = edge_src(ei, e);
}

// ---------------------------------------------------------------
// fused GAT softmax + aggregate (warp per dst, CSR). SINGLE PASS:
// acc += p_e * h_e and den += p_e together; normalize at the end.
// Optional next-layer esed from in-register output; fp16 output.
// ---------------------------------------------------------------
template<int DIM, bool RELU, bool ESED_NEXT>
__global__ __launch_bounds__(256) void k_gat_agg(
    const __half* __restrict__ h16, const float* __restrict__ es,
    const float* __restrict__ ed, const int* __restrict__ rowp,
    const int* __restrict__ csrc, const float* __restrict__ bias,
    __half* __restrict__ outH,
    const float* __restrict__ wsN, const float* __restrict__ wdN,
    float* __restrict__ esN, float* __restrict__ edN)
{
    constexpr int NH = DIM / 32;
    int w    = (blockIdx.x * blockDim.x + threadIdx.x) >> 5;
    int lane = threadIdx.x & 31;
    if (w >= NN) return;

    int start = rowp[w];
    int end   = rowp[w + 1];
    float edv = ed[w];

    float den = 0.f;
    float acc[NH] = {};
    for (int base = start; base < end; base += 32) {
        int e = base + lane;
        int sl = 0;
        float p = 0.f;
        if (e < end) {
            sl = csrc[e];
            float x = es[sl] + edv;
            x = (x >= 0.f) ? x : 0.2f * x;
            p = __expf(x);
        }
        den += p;
        int cnt = min(32, end - base);
        int j = 0;
        for (; j + 2 <= cnt; j += 2) {
            int   s0 = __shfl_sync(0xffffffffu, sl, j);
            float a0 = __shfl_sync(0xffffffffu, p,  j);
            int   s1 = __shfl_sync(0xffffffffu, sl, j + 1);
            float a1 = __shfl_sync(0xffffffffu, p,  j + 1);
            if (NH == 8) {
                uint4 r0 = *reinterpret_cast<const uint4*>(h16 + (size_t)s0 * DIM + lane * 8);
                uint4 r1 = *reinterpret_cast<const uint4*>(h16 + (size_t)s1 * DIM + lane * 8);
                const __half2* q0 = reinterpret_cast<const __half2*>(&r0);
                const __half2* q1 = reinterpret_cast<const __half2*>(&r1);
                #pragma unroll
                for (int t = 0; t < 4; t++) {
                    float2 f0 = __half22float2(q0[t]);
                    float2 f1 = __half22float2(q1[t]);
                    acc[t * 2 + 0] += a0 * f0.x + a1 * f1.x;
                    acc[t * 2 + 1] += a0 * f0.y + a1 * f1.y;
                }
            } else {
                uint2 r0 = *reinterpret_cast<const uint2*>(h16 + (size_t)s0 * DIM + lane * 4);
                uint2 r1 = *reinterpret_cast<const uint2*>(h16 + (size_t)s1 * DIM + lane * 4);
                const __half2* q0 = reinterpret_cast<const __half2*>(&r0);
                const __half2* q1 = reinterpret_cast<const __half2*>(&r1);
                #pragma unroll
                for (int t = 0; t < 2; t++) {
                    float2 f0 = __half22float2(q0[t]);
                    float2 f1 = __half22float2(q1[t]);
                    acc[t * 2 + 0] += a0 * f0.x + a1 * f1.x;
                    acc[t * 2 + 1] += a0 * f0.y + a1 * f1.y;
                }
            }
        }
        for (; j < cnt; j++) {
            int   s0 = __shfl_sync(0xffffffffu, sl, j);
            float a0 = __shfl_sync(0xffffffffu, p,  j);
            if (NH == 8) {
                uint4 r0 = *reinterpret_cast<const uint4*>(h16 + (size_t)s0 * DIM + lane * 8);
                const __half2* q0 = reinterpret_cast<const __half2*>(&r0);
                #pragma unroll
                for (int t = 0; t < 4; t++) {
                    float2 f0 = __half22float2(q0[t]);
                    acc[t * 2 + 0] += a0 * f0.x;
                    acc[t * 2 + 1] += a0 * f0.y;
                }
            } else {
                uint2 r0 = *reinterpret_cast<const uint2*>(h16 + (size_t)s0 * DIM + lane * 4);
                const __half2* q0 = reinterpret_cast<const __half2*>(&r0);
                #pragma unroll
                for (int t = 0; t < 2; t++) {
                    float2 f0 = __half22float2(q0[t]);
                    acc[t * 2 + 0] += a0 * f0.x;
                    acc[t * 2 + 1] += a0 * f0.y;
                }
            }
        }
    }

    // warp-reduce den, normalize, bias(+relu)
    #pragma unroll
    for (int o = 16; o; o >>= 1) den += __shfl_xor_sync(0xffffffffu, den, o);
    float inv = 1.f / den;

    const float* bp = bias + lane * NH;
    float v[NH];
    #pragma unroll
    for (int t4 = 0; t4 < NH / 4; t4++) {
        float4 b = *reinterpret_cast<const float4*>(bp + t4 * 4);
        v[t4 * 4 + 0] = acc[t4 * 4 + 0] * inv + b.x;
        v[t4 * 4 + 1] = acc[t4 * 4 + 1] * inv + b.y;
        v[t4 * 4 + 2] = acc[t4 * 4 + 2] * inv + b.z;
        v[t4 * 4 + 3] = acc[t4 * 4 + 3] * inv + b.w;
    }
    if (RELU) {
        #pragma unroll
        for (int t = 0; t < NH; t++) v[t] = fmaxf(v[t], 0.f);
    }

    if (ESED_NEXT) {
        float s = 0.f, d = 0.f;
        #pragma unroll
        for (int t4 = 0; t4 < NH / 4; t4++) {
            float4 a = *reinterpret_cast<const float4*>(wsN + lane * NH + t4 * 4);
            float4 b = *reinterpret_cast<const float4*>(wdN + lane * NH + t4 * 4);
            s += v[t4 * 4 + 0] * a.x + v[t4 * 4 + 1] * a.y + v[t4 * 4 + 2] * a.z + v[t4 * 4 + 3] * a.w;
            d += v[t4 * 4 + 0] * b.x + v[t4 * 4 + 1] * b.y + v[t4 * 4 + 2] * b.z + v[t4 * 4 + 3] * b.w;
        }
        #pragma unroll
        for (int o = 16; o; o >>= 1) {
            s += __shfl_xor_sync(0xffffffffu, s, o);
            d += __shfl_xor_sync(0xffffffffu, d, o);
        }
        if (lane == 0) { esN[w] = s; edN[w] = d; }
    }

    __half* op = outH + (size_t)w * DIM + lane * NH;
    __half2 hh[NH / 2];
    #pragma unroll
    for (int t = 0; t < NH / 2; t++) hh[t] = __floats2half2_rn(v[t * 2], v[t * 2 + 1]);
    if (NH == 8) *reinterpret_cast<uint4*>(op) = *reinterpret_cast<uint4*>(hh);
    else         *reinterpret_cast<uint2*>(op) = *reinterpret_cast<uint2*>(hh);
}

// ---------------------------------------------------------------
// link predictor (warp/pair, fp16 h)
// ---------------------------------------------------------------
__global__ __launch_bounds__(256) void k_link_pred(
    const __half* __restrict__ h, const int* __restrict__ mask,
    const float* __restrict__ Wl, const float* __restrict__ bl,
    float* __restrict__ out)
{
    int warp = (blockIdx.x * blockDim.x + threadIdx.x) >> 5;
    int lane = threadIdx.x & 31;
    if (warp >= PP) return;
    int m0 = mask[warp * 2 + 0];
    int m1 = mask[warp * 2 + 1];
    uint2 r0 = *reinterpret_cast<const uint2*>(h + (size_t)m0 * FIN + lane * 4);
    uint2 r1 = *reinterpret_cast<const uint2*>(h + (size_t)m1 * FIN + lane * 4);
    float4 w0 = *reinterpret_cast<const float4*>(Wl + lane * 4);
    float4 w1 = *reinterpret_cast<const float4*>(Wl + FIN + lane * 4);
    const __half2* q0 = reinterpret_cast<const __half2*>(&r0);
    const __half2* q1 = reinterpret_cast<const __half2*>(&r1);
    float2 a0 = __half22float2(q0[0]), a1 = __half22float2(q0[1]);
    float2 b0 = __half22float2(q1[0]), b1 = __half22float2(q1[1]);
    float acc = a0.x * w0.x + a0.y * w0.y + a1.x * w0.z + a1.y * w0.w
              + b0.x * w1.x + b0.y * w1.y + b1.x * w1.z + b1.y * w1.w;
    #pragma unroll
    for (int o = 16; o; o >>= 1) acc += __shfl_xor_sync(0xffffffffu, acc, o);
    if (lane == 0) out[warp] = 1.f / (1.f + __expf(-(acc + bl[0])));
}

// ---------------------------------------------------------------
extern "C" void kernel_launch(void* const* d_in, const int* in_sizes, int n_in,
                              void* d_out, int out_size)
{
    const float* features = (const float*)d_in[0];
    const int*   ei       = (const int*)  d_in[1];
    const int*   mask     = (const int*)  d_in[2];
    const float* W1       = (const float*)d_in[3];
    const float* a_src1   = (const float*)d_in[4];
    const float* a_dst1   = (const float*)d_in[5];
    const float* b1       = (const float*)d_in[6];
    const float* W2       = (const float*)d_in[7];
    const float* a_src2   = (const float*)d_in[8];
    const float* a_dst2   = (const float*)d_in[9];
    const float* b2       = (const float*)d_in[10];
    const float* Wl       = (const float*)d_in[11];
    const float* bl       = (const float*)d_in[12];
    float* out = (float*)d_out;

    __half *f16, *h1, *r16, *h2, *w1h, *w2h;
    float  *ws1, *wd1, *ws2, *wd2, *es1, *ed1, *es2, *ed2;
    int *deg, *rowp, *curs, *csrc;
    cudaGetSymbolAddress((void**)&f16,  g_f16);
    cudaGetSymbolAddress((void**)&h1,   g_h1);
    cudaGetSymbolAddress((void**)&r16,  g_r16);
    cudaGetSymbolAddress((void**)&h2,   g_h2);
    cudaGetSymbolAddress((void**)&w1h,  g_w1h);
    cudaGetSymbolAddress((void**)&w2h,  g_w2h);
    cudaGetSymbolAddress((void**)&ws1,  g_ws1);
    cudaGetSymbolAddress((void**)&wd1,  g_wd1);
    cudaGetSymbolAddress((void**)&ws2,  g_ws2);
    cudaGetSymbolAddress((void**)&wd2,  g_wd2);
    cudaGetSymbolAddress((void**)&es1,  g_es1);
    cudaGetSymbolAddress((void**)&ed1,  g_ed1);
    cudaGetSymbolAddress((void**)&es2,  g_es2);
    cudaGetSymbolAddress((void**)&ed2,  g_ed2);
    cudaGetSymbolAddress((void**)&deg,  g_deg);
    cudaGetSymbolAddress((void**)&rowp, g_rowp);
    cudaGetSymbolAddress((void**)&curs, g_curs);
    cudaGetSymbolAddress((void**)&csrc, g_csrc);

    const int edgeBlocks     = (ETOT + 255) / 256;
    const int nodeWarpBlocks = (NN * 32 + 255) / 256;

    // fork: CSR chain on side stream (depends only on ei)
    cudaEventRecord(hx.e0, 0);
    cudaStreamWaitEvent(hx.s1, hx.e0, 0);

    // main: (1) prep  (2) feat+esed1
    k_prep<<<80, 256>>>(W1, W2, a_src1, a_dst1, a_src2, a_dst2,
                        w1h, w2h, ws1, wd1, ws2, wd2);
    k_feat_esed<<<nodeWarpBlocks, 256>>>(features, f16, ws1, wd1, es1, ed1);
    // side: (3) zero deg
    k_zero<<<(NN + 255) / 256, 256, 0, hx.s1>>>(deg);
    // main: (4) gemm1  [profiler slot]
    {
        dim3 g(HH / 128, (NN + 127) / 128);
        k_gemm16<FIN, HH><<<g, 256>>>(f16, w1h, h1, NN);
    }
    // side: (5..7) hist, scan, scatter
    k_hist      <<<edgeBlocks, 256, 0, hx.s1>>>(ei, deg);
    k_scan_fused<<<1, SCAN_T, 0, hx.s1>>>(deg, rowp, curs);
    k_scatter   <<<edgeBlocks, 256, 0, hx.s1>>>(ei, curs, csrc);
    cudaEventRecord(hx.e1, hx.s1);

    // join before aggregation
    cudaStreamWaitEvent(0, hx.e1, 0);

    // (8) aggregate layer1 -> relu -> fp16, + fused esed2 (single pass)
    k_gat_agg<HH, true, true><<<nodeWarpBlocks, 256>>>(
        h1, es1, ed1, rowp, csrc, b1, r16, ws2, wd2, es2, ed2);
    // (9) gemm2
    {
        dim3 g(FIN / 128, (NN + 127) / 128);
        k_gemm16<HH, FIN><<<g, 256>>>(r16, w2h, h2, NN);
    }
    // (10) aggregate layer2 -> fp16 (reuse f16 buffer)
    k_gat_agg<FIN, false, false><<<nodeWarpBlocks, 256>>>(
        h2, es2, ed2, rowp, csrc, b2, f16, nullptr, nullptr, nullptr, nullptr);
    // (11) link predictor
    k_link_pred<<<(PP * 32 + 255) / 256, 256>>>(f16, mask, Wl, bl, out);
}